// round 4
// baseline (speedup 1.0000x reference)
#include <cuda_runtime.h>
#include <math.h>

#define T_SEQ   4096
#define NNODES  64
#define FPL     8
#define OBS_DIM 512
#define HID     64
#define GATES   256
#define FULLMASK 0xffffffffu

// scratch (static device allocations — allowed)
__device__ float g_hs[T_SEQ * NNODES * HID];            // 64 MB: h[t][n][k]
__device__ float g_xproj[(T_SEQ + 2) * NNODES * GATES]; // 268 MB: m*(b + W_ih·x), +2 pad steps
__device__ float g_Wg_t[HID * GATES];
__device__ float g_Wm_t[GATES * HID];
__device__ float g_Ws_t[GATES * HID];

typedef unsigned long long ull;

__device__ __forceinline__ void ffma2(ull& d, const ull a, const ull b) {
    asm("fma.rn.f32x2 %0, %1, %2, %0;" : "+l"(d) : "l"(a), "l"(b));
}
__device__ __forceinline__ ull addf2(ull a, ull b) {
    ull r; asm("add.rn.f32x2 %0, %1, %2;" : "=l"(r) : "l"(a), "l"(b)); return r;
}
__device__ __forceinline__ float2 unpack2(ull v) {
    float2 f; asm("mov.b64 {%0, %1}, %2;" : "=f"(f.x), "=f"(f.y) : "l"(v)); return f;
}
__device__ __forceinline__ ull pack2(float lo, float hi) {
    ull v; asm("mov.b64 %0, {%1, %2};" : "=l"(v) : "f"(lo), "f"(hi)); return v;
}
__device__ __forceinline__ float ex2f(float x) {
    float r; asm("ex2.approx.f32 %0, %1;" : "=f"(r) : "f"(x)); return r;
}
__device__ __forceinline__ float rcpf(float x) {
    float r; asm("rcp.approx.f32 %0, %1;" : "=f"(r) : "f"(x)); return r;
}
__device__ __forceinline__ float tanh_fast(float x) {
    return fmaf(rcpf(1.0f + ex2f(x * -2.8853900817779268f)), 2.0f, -1.0f);
}

#define M_SIG (-1.4426950408889634f)
#define M_TNH (-2.8853900817779268f)

// ---------------------------------------------------------------------------
// Kernel A: one-time weight transposes for head GEMVs
// ---------------------------------------------------------------------------
__global__ void transpose_kernel(const float* __restrict__ Wg,
                                 const float* __restrict__ Wm,
                                 const float* __restrict__ Ws)
{
    int i = blockIdx.x * 256 + threadIdx.x;
    if (i < GATES * HID) {
        int j = i >> 6, k = i & 63;
        g_Wg_t[k * GATES + j] = Wg[i];
        int a = i >> 8, jj = i & 255;
        g_Wm_t[jj * HID + a] = Wm[i];
        g_Ws_t[jj * HID + a] = Ws[i];
    }
}

// ---------------------------------------------------------------------------
// Kernel B: xproj[t][n][r] = m(r) * (b_ih[r] + b_hh[r] + W_ih[r,:]·x[t, n*8:+8])
// One CTA per timestep; thread = gate row r; loops over nodes.
// ---------------------------------------------------------------------------
__global__ void __launch_bounds__(256, 4)
xproj_kernel(const float* __restrict__ x,
             const float* __restrict__ W_ih,
             const float* __restrict__ b_ih,
             const float* __restrict__ b_hh)
{
    const int t = blockIdx.x;
    const int r = threadIdx.x;
    const int gate = r >> 6;
    const float m = (gate == 2) ? M_TNH : M_SIG;

    __shared__ __align__(16) float xs[OBS_DIM];

    // stage x[t] (512 floats)
    {
        const float4* src = (const float4*)(x + t * OBS_DIM);
        float4* dst = (float4*)xs;
        if (r < OBS_DIM / 4) dst[r] = src[r];
    }
    float w[FPL];
#pragma unroll
    for (int j = 0; j < FPL; j++) w[j] = W_ih[r * FPL + j] * m;
    const float bm = (b_ih[r] + b_hh[r]) * m;
    __syncthreads();

    float* outp = g_xproj + (t * NNODES) * GATES + r;
#pragma unroll 4
    for (int n = 0; n < NNODES; n++) {
        const float* xv = xs + n * FPL;
        float acc = bm;
#pragma unroll
        for (int j = 0; j < FPL; j++) acc += w[j] * xv[j];
        outp[n * GATES] = acc;
    }
}

// ---------------------------------------------------------------------------
// Kernel C: LSTMs. 32 CTAs x 512 threads; each CTA runs TWO independent nodes
// (interleaved recurrences -> dependency stalls of one fill pipe slots of the
// other). Thread wtid -> (k = wtid>>2, gate = wtid&3), row r = gate*64+k.
// Input projection + bias pre-folded & pre-scaled in g_xproj.
// ---------------------------------------------------------------------------
__global__ void __launch_bounds__(512, 1)
lstm_kernel(const float* __restrict__ W_hh,
            float* __restrict__ out)
{
    const int tid  = threadIdx.x;
    const int nloc = tid >> 8;                 // 0/1: which node in this CTA
    const int n    = blockIdx.x * 2 + nloc;
    const int wtid = tid & 255;
    const int k    = wtid >> 2;
    const int gate = wtid & 3;
    const int r    = gate * HID + k;
    const unsigned lane = tid & 31u;
    const unsigned lb   = lane & ~3u;

    const bool  is_g = (gate == 2);
    const float m    = is_g ? M_TNH : M_SIG;
    const float Aact = is_g ?  2.0f : 1.0f;
    const float Bact = is_g ? -1.0f : 0.0f;

    __shared__ __align__(16) float h2[2][2][HID];   // [nloc][parity][k]

    // W_hh row in registers, pre-scaled by m, packed f32x2
    ull whh[32];
    {
        const float* wrow = W_hh + r * HID;
#pragma unroll
        for (int i = 0; i < 32; i++)
            whh[i] = pack2(wrow[2*i] * m, wrow[2*i+1] * m);
    }

    float c_reg = 0.0f;
    if (wtid < HID) h2[nloc][0][wtid] = 0.0f;

    // xproj stream: stride 16384 floats per step; 2-step-deep prefetch
    const float* xpro = g_xproj + n * GATES + r;
    float xp0 = xpro[0];
    float xp1 = xpro[NNODES * GATES];
    __syncthreads();

    float* hs_out = g_hs + n * HID + k;

#pragma unroll 4
    for (int t = 0; t < T_SEQ; t++) {
        const int par = t & 1;

        // init accumulator with prefetched m*(b + W_ih·x); rotate prefetch
        ull a0 = pack2(xp0, 0.0f), a1 = 0, a2 = 0, a3 = 0;
        ull a4 = 0, a5 = 0, a6 = 0, a7 = 0;
        xp0 = xp1;
        xp1 = xpro[(t + 2) * (NNODES * GATES)];   // pad rows make this safe

        const ulonglong2* hp = (const ulonglong2*)h2[nloc][par];
#pragma unroll
        for (int mm = 0; mm < 4; mm++) {
            ulonglong2 hv0 = hp[4*mm + 0], hv1 = hp[4*mm + 1];
            ulonglong2 hv2 = hp[4*mm + 2], hv3 = hp[4*mm + 3];
            ffma2(a0, whh[8*mm+0], hv0.x);
            ffma2(a1, whh[8*mm+1], hv0.y);
            ffma2(a2, whh[8*mm+2], hv1.x);
            ffma2(a3, whh[8*mm+3], hv1.y);
            ffma2(a4, whh[8*mm+4], hv2.x);
            ffma2(a5, whh[8*mm+5], hv2.y);
            ffma2(a6, whh[8*mm+6], hv3.x);
            ffma2(a7, whh[8*mm+7], hv3.y);
        }
        // packed reduction tree
        ull b0 = addf2(a0, a1), b1 = addf2(a2, a3);
        ull b2 = addf2(a4, a5), b3 = addf2(a6, a7);
        ull c0 = addf2(b0, b1), c1 = addf2(b2, b3);
        float2 f = unpack2(addf2(c0, c1));
        const float accv = f.x + f.y;

        // branch-free activation: v = A * RCP(1 + EX2(acc)) + B
        const float v = fmaf(rcpf(1.0f + ex2f(accv)), Aact, Bact);

        // gather i,f,g,o within the quad
        const float vi = __shfl_sync(FULLMASK, v, lb);
        const float vf = __shfl_sync(FULLMASK, v, lb | 1);
        const float vg = __shfl_sync(FULLMASK, v, lb | 2);
        const float vo = __shfl_sync(FULLMASK, v, lb | 3);

        if (gate == 0) {
            c_reg = vf * c_reg + vi * vg;
            const float h = vo * tanh_fast(c_reg);
            h2[nloc][par ^ 1][k] = h;
            hs_out[t * (NNODES * HID)] = h;
        }
        __syncthreads();
    }

    // hn / cn
    if (gate == 0) {
        const int base = 2 * T_SEQ * NNODES;
        out[base + n * HID + k] = h2[nloc][0][k];
        out[base + NNODES * HID + n * HID + k] = c_reg;
    }
}

// ---------------------------------------------------------------------------
// Kernel D: fused mean-pool + head (identity-GAT collapse), 64 CTAs x 64 t.
// ---------------------------------------------------------------------------
__global__ void __launch_bounds__(256, 1)
head_kernel(const float* __restrict__ b_gat,
            const float* __restrict__ b_mean,
            const float* __restrict__ b_std,
            float* __restrict__ out)
{
    const int t0  = blockIdx.x * 64;
    const int tid = threadIdx.x;

    __shared__ __align__(16) float hbar_s[64][HID];
    __shared__ float g_s[GATES];

    {
        const int k = tid & 63, q = tid >> 6;
#pragma unroll
        for (int i = 0; i < 16; i++) {
            const int tl = q + 4 * i;
            const float* base = g_hs + ((long)(t0 + tl) * NNODES) * HID + k;
            float s = 0.0f;
#pragma unroll 8
            for (int nn = 0; nn < NNODES; nn++) s += base[nn * HID];
            hbar_s[tl][k] = s * (1.0f / 64.0f);
        }
    }
    __syncthreads();

    const float bg = b_gat[tid];
    for (int i = 0; i < 64; i++) {
        const int t = t0 + i;
        {
            float acc = bg;
            const float* hb = hbar_s[i];
#pragma unroll
            for (int k = 0; k < HID; k++) acc += g_Wg_t[k * GATES + tid] * hb[k];
            g_s[tid] = fmaxf(acc, 0.0f);
        }
        __syncthreads();

        if (tid < 128) {
            const int  a      = tid & 63;
            const bool is_std = (tid >= 64);
            const float* Wt = is_std ? g_Ws_t : g_Wm_t;
            float acc = is_std ? b_std[a] : b_mean[a];
#pragma unroll 8
            for (int j = 0; j < GATES; j++) acc += Wt[j * HID + a] * g_s[j];
            if (is_std) {
                float sp = (acc > 20.0f) ? acc : log1pf(__expf(acc));
                sp = fminf(fmaxf(sp, 0.001f), 10.0f);
                out[T_SEQ * NNODES + t * NNODES + a] = sp;
            } else {
                out[t * NNODES + a] = acc;
            }
        }
        __syncthreads();
    }
}

// ---------------------------------------------------------------------------
// launch
// ---------------------------------------------------------------------------
extern "C" void kernel_launch(void* const* d_in, const int* in_sizes, int n_in,
                              void* d_out, int out_size)
{
    const float* x      = (const float*)d_in[0];
    const float* W_ih   = (const float*)d_in[1];
    const float* W_hh   = (const float*)d_in[2];
    const float* b_ih   = (const float*)d_in[3];
    const float* b_hh   = (const float*)d_in[4];
    const float* W_gat  = (const float*)d_in[5];
    // d_in[6], d_in[7] (att_src/att_dst) provably unused: identity adjacency
    // -> softmax over a single unmasked element == 1 for any logits.
    const float* b_gat  = (const float*)d_in[8];
    // const float* W_mean/W_std folded via transpose
    const float* b_mean = (const float*)d_in[10];
    const float* b_std  = (const float*)d_in[12];
    float* out = (float*)d_out;

    transpose_kernel<<<64, 256>>>(W_gat, (const float*)d_in[9], (const float*)d_in[11]);
    xproj_kernel<<<T_SEQ, 256>>>(x, W_ih, b_ih, b_hh);
    lstm_kernel<<<NNODES / 2, 512>>>(W_hh, out);
    head_kernel<<<T_SEQ / 64, 256>>>(b_gat, b_mean, b_std, out);
}

// round 6
// speedup vs baseline: 1.8682x; 1.8682x over previous
#include <cuda_runtime.h>
#include <cstdint>
#include <math.h>

#define T_SEQ   4096
#define NNODES  64
#define FPL     8
#define OBS_DIM 512
#define HID     64
#define GATES   256
#define FULLMASK 0xffffffffu

// scratch (static device allocations — allowed)
__device__ float g_hs[T_SEQ * NNODES * HID];   // 64 MB: h[t][n][k]
__device__ float g_Wg_t[HID * GATES];
__device__ float g_Wm_t[GATES * HID];
__device__ float g_Ws_t[GATES * HID];

typedef unsigned long long ull;
typedef unsigned int u32;

__device__ __forceinline__ void ffma2(ull& d, const ull a, const ull b) {
    asm("fma.rn.f32x2 %0, %1, %2, %0;" : "+l"(d) : "l"(a), "l"(b));
}
__device__ __forceinline__ ull addf2(ull a, ull b) {
    ull r; asm("add.rn.f32x2 %0, %1, %2;" : "=l"(r) : "l"(a), "l"(b)); return r;
}
__device__ __forceinline__ float2 unpack2(ull v) {
    float2 f; asm("mov.b64 {%0, %1}, %2;" : "=f"(f.x), "=f"(f.y) : "l"(v)); return f;
}
__device__ __forceinline__ ull pack2(float lo, float hi) {
    ull v; asm("mov.b64 %0, {%1, %2};" : "=l"(v) : "f"(lo), "f"(hi)); return v;
}
__device__ __forceinline__ float ex2f(float x) {
    float r; asm("ex2.approx.f32 %0, %1;" : "=f"(r) : "f"(x)); return r;
}
__device__ __forceinline__ float rcpf(float x) {
    float r; asm("rcp.approx.f32 %0, %1;" : "=f"(r) : "f"(x)); return r;
}
__device__ __forceinline__ float tanh_fast(float x) {
    return fmaf(rcpf(1.0f + ex2f(x * -2.8853900817779268f)), 2.0f, -1.0f);
}
__device__ __forceinline__ u32 smem_u32(const void* p) {
    u32 a;
    asm("{ .reg .u64 t; cvta.to.shared.u64 t, %1; cvt.u32.u64 %0, t; }"
        : "=r"(a) : "l"(p));
    return a;
}

#define M_SIG (-1.4426950408889634f)
#define M_TNH (-2.8853900817779268f)

// ---------------------------------------------------------------------------
// Kernel A: one-time weight transposes for head GEMVs
// ---------------------------------------------------------------------------
__global__ void transpose_kernel(const float* __restrict__ Wg,
                                 const float* __restrict__ Wm,
                                 const float* __restrict__ Ws)
{
    int i = blockIdx.x * 256 + threadIdx.x;
    if (i < GATES * HID) {
        int j = i >> 6, k = i & 63;
        g_Wg_t[k * GATES + j] = Wg[i];
        int a = i >> 8, jj = i & 255;
        g_Wm_t[jj * HID + a] = Wm[i];
        g_Ws_t[jj * HID + a] = Ws[i];
    }
}

// ---------------------------------------------------------------------------
// Kernel B: 64 independent LSTMs, one CTA per node, 256 threads, T=4096.
// Thread tid -> (k = tid>>2, gate = tid&3), row r = gate*64 + k.
// Branch-free step body: pre-scaled weights make activation EX2->RCP->FMA;
// all lanes redundantly compute c/h (quad-identical); stores are
// inline-asm predicated (@p STS/STG) so ptxas emits NO BSSY/BSYNC.
// ---------------------------------------------------------------------------
__global__ void __launch_bounds__(256, 1)
lstm_kernel(const float* __restrict__ x,
            const float* __restrict__ W_ih,
            const float* __restrict__ W_hh,
            const float* __restrict__ b_ih,
            const float* __restrict__ b_hh,
            float* __restrict__ out)
{
    const int n    = blockIdx.x;
    const int tid  = threadIdx.x;
    const int k    = tid >> 2;
    const int gate = tid & 3;
    const int r    = gate * HID + k;
    const unsigned lane = tid & 31u;
    const unsigned lb   = lane & ~3u;

    const bool  is_g = (gate == 2);
    const float m    = is_g ? M_TNH : M_SIG;
    const float Aact = is_g ?  2.0f : 1.0f;
    const float Bact = is_g ? -1.0f : 0.0f;

    __shared__ __align__(16) float h2[2][HID];
    __shared__ __align__(16) float xs[2][32][FPL];

    // weights in registers, pre-scaled by m, packed f32x2
    ull whh[32];
    {
        const float* wrow = W_hh + r * HID;
#pragma unroll
        for (int i = 0; i < 32; i++)
            whh[i] = pack2(wrow[2*i] * m, wrow[2*i+1] * m);
    }
    ull wih[4];
    {
        const float* wrow = W_ih + r * FPL;
#pragma unroll
        for (int i = 0; i < 4; i++)
            wih[i] = pack2(wrow[2*i] * m, wrow[2*i+1] * m);
    }
    const float bsum = (b_ih[r] + b_hh[r]) * m;

    const u32 h2_base = smem_u32(h2);       // smem address of h2[0][0]
    float c_reg = 0.0f;
    if (tid < HID) h2[0][tid] = 0.0f;

    // prologue: stage x batch 0
    {
        int s = tid >> 3, j = tid & 7;
        xs[0][s][j] = x[s * OBS_DIM + n * FPL + j];
    }
    __syncthreads();

    // g_hs write pointer for this thread (gate-0 lanes are the real writers)
    const float* hs_ptr = g_hs + n * HID + k;

    for (int b = 0; b < T_SEQ / 32; b++) {
        // prefetch next x batch into a register (hidden over 32 steps)
        float xpref = 0.0f;
        {
            int tn = (b + 1) * 32 + (tid >> 3);
            if (tn < T_SEQ) xpref = x[tn * OBS_DIM + n * FPL + (tid & 7)];
        }
#pragma unroll 4
        for (int s = 0; s < 32; s++) {
            const int par = s & 1;

            // acc = m*(bias + W_ih·x + W_hh·h)   (8 packed accumulators)
            ull a0 = pack2(bsum, 0.0f), a1 = 0, a2 = 0, a3 = 0;
            ull a4 = 0, a5 = 0, a6 = 0, a7 = 0;
            {
                const ulonglong2* xp = (const ulonglong2*)xs[b & 1][s];
                ulonglong2 xv0 = xp[0], xv1 = xp[1];
                ffma2(a0, wih[0], xv0.x);
                ffma2(a2, wih[1], xv0.y);
                ffma2(a4, wih[2], xv1.x);
                ffma2(a6, wih[3], xv1.y);
            }
            const ulonglong2* hp = (const ulonglong2*)h2[par];
#pragma unroll
            for (int mm = 0; mm < 4; mm++) {
                ulonglong2 hv0 = hp[4*mm + 0], hv1 = hp[4*mm + 1];
                ulonglong2 hv2 = hp[4*mm + 2], hv3 = hp[4*mm + 3];
                ffma2(a0, whh[8*mm+0], hv0.x);
                ffma2(a1, whh[8*mm+1], hv0.y);
                ffma2(a2, whh[8*mm+2], hv1.x);
                ffma2(a3, whh[8*mm+3], hv1.y);
                ffma2(a4, whh[8*mm+4], hv2.x);
                ffma2(a5, whh[8*mm+5], hv2.y);
                ffma2(a6, whh[8*mm+6], hv3.x);
                ffma2(a7, whh[8*mm+7], hv3.y);
            }
            // packed reduction tree
            ull b0 = addf2(a0, a1), b1 = addf2(a2, a3);
            ull b2 = addf2(a4, a5), b3 = addf2(a6, a7);
            float2 f = unpack2(addf2(addf2(b0, b1), addf2(b2, b3)));
            const float accv = f.x + f.y;

            // branch-free activation: v = A * RCP(1 + EX2(acc)) + B
            const float v = fmaf(rcpf(1.0f + ex2f(accv)), Aact, Bact);

            // gather i,f,g,o within the quad (independent shuffles)
            const float vi = __shfl_sync(FULLMASK, v, lb);
            const float vf = __shfl_sync(FULLMASK, v, lb | 1);
            const float vg = __shfl_sync(FULLMASK, v, lb | 2);
            const float vo = __shfl_sync(FULLMASK, v, lb | 3);

            // ALL lanes compute c/h (identical within the quad) — no branch
            c_reg = vf * c_reg + vi * vg;
            const float h = vo * tanh_fast(c_reg);

            // predicated stores (no BSSY/BSYNC): only gate==0 lanes commit
            {
                const u32 sts_addr = h2_base + (u32)((((par ^ 1) * HID) + k) * 4);
                asm volatile(
                    "{ .reg .pred p; setp.eq.s32 p, %0, 0;\n\t"
                    "@p st.shared.f32 [%1], %3;\n\t"
                    "@p st.global.f32 [%2], %3; }"
                    :: "r"(gate), "r"(sts_addr), "l"(hs_ptr), "f"(h)
                    : "memory");
            }
            hs_ptr += NNODES * HID;

            // stage next x batch mid-way (write-only buffer this batch)
            if (s == 20) xs[(b + 1) & 1][tid >> 3][tid & 7] = xpref;
            __syncthreads();
        }
    }

    // hn / cn (t=4095 wrote parity (4095&1)^1 = h2[0])
    if (gate == 0) {
        const int base = 2 * T_SEQ * NNODES;
        out[base + n * HID + k] = h2[0][k];
        out[base + NNODES * HID + n * HID + k] = c_reg;
    }
}

// ---------------------------------------------------------------------------
// Kernel C: warp-autonomous head. 512 CTAs x 8 warps; ONE WARP PER TIMESTEP.
// No block barriers, no serialization; weights L1-resident (transposed).
// GAT collapses to identity-attention; mean-pool commutes with W_gat.
// ---------------------------------------------------------------------------
__global__ void __launch_bounds__(256, 2)
head_kernel(const float* __restrict__ b_gat,
            const float* __restrict__ b_mean,
            const float* __restrict__ b_std,
            float* __restrict__ out)
{
    const int w    = threadIdx.x >> 5;
    const int lane = threadIdx.x & 31;
    const int t    = blockIdx.x * 8 + w;

    __shared__ __align__(16) float hb[8][HID];     // 2 KB
    __shared__ __align__(16) float gs[8][GATES];   // 8 KB

    // Phase 1: hbar[k] = mean_n h[t][n][k]  (warp reads 16 KB, MLP-rich)
    {
        const float* p = g_hs + (long)t * (NNODES * HID);
        float s0 = 0.0f, s1 = 0.0f;
#pragma unroll 8
        for (int n = 0; n < NNODES; n++) {
            s0 += p[n * HID + lane];
            s1 += p[n * HID + 32 + lane];
        }
        hb[w][lane]      = s0 * (1.0f / 64.0f);
        hb[w][32 + lane] = s1 * (1.0f / 64.0f);
    }
    __syncwarp();

    // Phase 2: g[j] = relu(W_gat[j,:]·hbar + b_gat[j]), 8 outputs per lane
#pragma unroll
    for (int i = 0; i < 8; i++) {
        const int j = i * 32 + lane;
        float acc = b_gat[j];
#pragma unroll 8
        for (int k = 0; k < HID; k++)
            acc += g_Wg_t[k * GATES + j] * hb[w][k];
        gs[w][j] = fmaxf(acc, 0.0f);
    }
    __syncwarp();

    // Phase 3: mean / std heads, 2 outputs each per lane
#pragma unroll
    for (int i = 0; i < 2; i++) {
        const int a = i * 32 + lane;
        float am = b_mean[a], as = b_std[a];
#pragma unroll 8
        for (int j = 0; j < GATES; j++) {
            const float gv = gs[w][j];
            am += g_Wm_t[j * HID + a] * gv;
            as += g_Ws_t[j * HID + a] * gv;
        }
        out[t * NNODES + a] = am;
        float sp = (as > 20.0f) ? as : log1pf(__expf(as));
        out[T_SEQ * NNODES + t * NNODES + a] = fminf(fmaxf(sp, 0.001f), 10.0f);
    }
}

// ---------------------------------------------------------------------------
// launch
// ---------------------------------------------------------------------------
extern "C" void kernel_launch(void* const* d_in, const int* in_sizes, int n_in,
                              void* d_out, int out_size)
{
    const float* x      = (const float*)d_in[0];
    const float* W_ih   = (const float*)d_in[1];
    const float* W_hh   = (const float*)d_in[2];
    const float* b_ih   = (const float*)d_in[3];
    const float* b_hh   = (const float*)d_in[4];
    const float* W_gat  = (const float*)d_in[5];
    // d_in[6], d_in[7] (att_src/att_dst) provably unused: identity adjacency
    // -> softmax over a single unmasked element == 1 for any logits.
    const float* b_gat  = (const float*)d_in[8];
    const float* b_mean = (const float*)d_in[10];
    const float* b_std  = (const float*)d_in[12];
    float* out = (float*)d_out;

    transpose_kernel<<<64, 256>>>(W_gat, (const float*)d_in[9], (const float*)d_in[11]);
    lstm_kernel<<<NNODES, 256>>>(x, W_ih, W_hh, b_ih, b_hh, out);
    head_kernel<<<T_SEQ / 8, 256>>>(b_gat, b_mean, b_std, out);
}